// round 11
// baseline (speedup 1.0000x reference)
#include <cuda_runtime.h>

// ---------------------------------------------------------------------------
// Pose2Mesh fully-collapsed linear implementation.
// All heads + neighbor 3x3 contractions + root subtraction folded into one
// dense W'(57 x 151) + b'(151); main kernel = out(B,151) = x(B,57) @ W' + b'.
// Kernels chained with programmatic dependent launch (upstream triggers at
// entry; griddepcontrol.wait enforces full upstream completion).
// ---------------------------------------------------------------------------

#define D_DIM   2048
#define NC      57      // J*3
#define NK      151
#define NKPAD   160
#define KSPLIT  64
#define KCHUNK  32      // D_DIM / KSPLIT
#define H_DIM   512
#define CPB     32      // cols per block (main)
#define NSLICES 5       // 160/32
#define RPB     64      // rows per block (main)
#define TPBM    256     // threads per block (main)

#define GDC_LAUNCH() asm volatile("griddepcontrol.launch_dependents;")
#define GDC_WAIT()   asm volatile("griddepcontrol.wait;" ::: "memory")

// scratch (allocation-free: __device__ globals)
__device__ float g_M1[24 * 9];
__device__ float g_M2[24 * 9];
__device__ float g_bp1[72];
__device__ float g_bp2[72];
__device__ float g_Wpart[KSPLIT * 58 * NKPAD];
__device__ float g_W[NC * NKPAD];
__device__ float g_b[NKPAD];

// NEB1[j]*3 and NEB2[j]*3 (base offsets into the 57-float joint vector)
__constant__ int c_NB1[24] = {51,33,36,51,39,42,51,45,48,54,45,48,54,54,54,54,15,18,21,24,27,30,27,30};
__constant__ int c_NB2[24] = {54,51,51,54,33,36,54,39,42,51,39,42, 0,15,18, 0,54,54,15,18,21,24,21,24};

// ---------------------------------------------------------------------------
// Kernel A (fused): blocks [0, 5*KSPLIT) = fold GEMM split-K partials,
//                   blocks [5*KSPLIT, +48) = per-(joint, side) M/bias dots
// ---------------------------------------------------------------------------
__device__ __forceinline__ float fetchB(int f, int col,
                                        const float* __restrict__ Wsh, const float* __restrict__ Wca,
                                        const float* __restrict__ Wph, const float* __restrict__ Wlf,
                                        const float* __restrict__ Rf)
{
    if (col < 10)  return Wsh[f * 10 + col];
    if (col < 13)  return Wca[f * 3  + (col - 10)];
    if (col < 59)  return Wph[f * 46 + (col - 13)];
    if (col < 79)  return Wlf[f * 20 + (col - 59)];
    int t = col - 79;
    int j = t / 3, o = t - j * 3;
    return Rf[(j * D_DIM + f) * 3 + o];
}

__global__ void __launch_bounds__(256)
precompute_kernel(const float* __restrict__ W_enc, const float* __restrict__ b_enc,
                  const float* __restrict__ W_shape, const float* __restrict__ W_cam,
                  const float* __restrict__ W_phi,   const float* __restrict__ W_leaf,
                  const float* __restrict__ Rf,
                  const float* __restrict__ L1_w, const float* __restrict__ L1_b,
                  const float* __restrict__ L2_w, const float* __restrict__ L2_b,
                  const float* __restrict__ R1,   const float* __restrict__ R2)
{
    GDC_LAUNCH();   // let finalize launch + prologue overlap our execution

    int bx  = blockIdx.x;
    int tid = threadIdx.x;

    if (bx >= 5 * KSPLIT) {
        // ---- M-part: 48 blocks = (j, s). Load L_s_w[j], L_s_b[j], R_s[j] ONCE
        // (coalesced float4 -> smem), then 12 dots (9 M + 3 bias) from smem.
        __shared__ __align__(16) float sLw[3 * H_DIM];   // 1536
        __shared__ __align__(16) float sR [H_DIM * 3];   // 1536
        __shared__ __align__(16) float sLb[H_DIM];       // 512

        int mb = bx - 5 * KSPLIT;         // 0..47
        int j  = mb >> 1;
        int s  = mb & 1;
        const float* Lw = (s ? L2_w : L1_w) + j * 3 * H_DIM;
        const float* Lb = (s ? L2_b : L1_b) + j * H_DIM;
        const float* Rm = (s ? R2   : R1  ) + j * H_DIM * 3;

        // 896 float4 total: 384 Lw + 384 R + 128 Lb; 4 per thread (guarded)
        float4 v[4];
        #pragma unroll
        for (int i = 0; i < 4; i++) {
            int idx = tid + 256 * i;
            if      (idx < 384) v[i] = *(const float4*)(Lw + idx * 4);
            else if (idx < 768) v[i] = *(const float4*)(Rm + (idx - 384) * 4);
            else if (idx < 896) v[i] = *(const float4*)(Lb + (idx - 768) * 4);
        }
        #pragma unroll
        for (int i = 0; i < 4; i++) {
            int idx = tid + 256 * i;
            if      (idx < 384) *(float4*)(sLw + idx * 4)         = v[i];
            else if (idx < 768) *(float4*)(sR  + (idx - 384) * 4) = v[i];
            else if (idx < 896) *(float4*)(sLb + (idx - 768) * 4) = v[i];
        }
        __syncthreads();

        int lane = tid & 31;
        int w    = tid >> 5;              // 0..7
        for (int t = w; t < 12; t += 8) {
            int c = (t < 9) ? (t / 3) : 0;
            int o = (t < 9) ? (t % 3) : (t - 9);
            const float* ap = (t < 9) ? (sLw + c * H_DIM) : sLb;
            float sum = 0.f;
            #pragma unroll
            for (int i = 0; i < 16; i++) {
                int h = lane + 32 * i;
                sum = fmaf(ap[h], sR[h * 3 + o], sum);
            }
            #pragma unroll
            for (int d = 16; d > 0; d >>= 1) sum += __shfl_xor_sync(0xffffffffu, sum, d);
            if (lane == 0) {
                if (t < 9) { if (s) g_M2[j * 9 + t] = sum; else g_M1[j * 9 + t] = sum; }
                else       { if (s) g_bp2[j * 3 + o] = sum; else g_bp1[j * 3 + o] = sum; }
            }
        }
        return;
    }

    // ---- fold GEMM: K=32 chunk per block, split-K partials
    __shared__ float As[64][KCHUNK + 1];
    __shared__ __align__(16) float Bs[KCHUNK][36];

    int ct = bx % 5;              // column tile (5 tiles of 32 -> 160)
    int ks = bx / 5;              // k-split index (0..63)
    int kbase = ks * KCHUNK;

    // batched A loads via float4: 58 rows x 8 float4 = 464, 256 thr -> 2 each
    float4 va[2];
    int    vr[2], vq[2];
    #pragma unroll
    for (int i = 0; i < 2; i++) {
        int idx = tid + 256 * i;
        int r = idx >> 3, q = idx & 7;
        vr[i] = r; vq[i] = q;
        float4 v4 = make_float4(0.f, 0.f, 0.f, 0.f);
        if (r < NC)       v4 = *(const float4*)(W_enc + r * D_DIM + kbase + q * 4);
        else if (r == NC) v4 = *(const float4*)(b_enc + kbase + q * 4);
        va[i] = v4;
    }
    // batched B loads (32*32 = 1024 / 256 = 4 each, gathered)
    float vb[4];
    #pragma unroll
    for (int i = 0; i < 4; i++) {
        int idx = tid + 256 * i;
        int kk = idx >> 5, cl = idx & 31;
        int gcol = ct * 32 + cl;
        vb[i] = (gcol < NK) ? fetchB(kbase + kk, gcol, W_shape, W_cam, W_phi, W_leaf, Rf) : 0.f;
    }
    #pragma unroll
    for (int i = 0; i < 2; i++) {
        if (vr[i] < 64) {
            float* dst = &As[vr[i]][vq[i] * 4];
            dst[0] = va[i].x; dst[1] = va[i].y; dst[2] = va[i].z; dst[3] = va[i].w;
        }
    }
    #pragma unroll
    for (int i = 0; i < 4; i++) {
        int idx = tid + 256 * i;
        Bs[idx >> 5][idx & 31] = vb[i];
    }
    __syncthreads();

    // compute: thread = (row r, col group cg of 8)
    int r  = tid >> 2;            // 0..63
    int cg = tid & 3;             // 0..3
    float acc[8];
    #pragma unroll
    for (int e = 0; e < 8; e++) acc[e] = 0.f;
    #pragma unroll
    for (int kk = 0; kk < KCHUNK; kk++) {
        float  xc = As[r][kk];
        float4 w0 = *(const float4*)&Bs[kk][cg * 8];
        float4 w1 = *(const float4*)&Bs[kk][cg * 8 + 4];
        acc[0] = fmaf(xc, w0.x, acc[0]); acc[1] = fmaf(xc, w0.y, acc[1]);
        acc[2] = fmaf(xc, w0.z, acc[2]); acc[3] = fmaf(xc, w0.w, acc[3]);
        acc[4] = fmaf(xc, w1.x, acc[4]); acc[5] = fmaf(xc, w1.y, acc[5]);
        acc[6] = fmaf(xc, w1.z, acc[6]); acc[7] = fmaf(xc, w1.w, acc[7]);
    }
    if (r < 58) {
        float* dst = &g_Wpart[(ks * 58 + r) * NKPAD + ct * 32 + cg * 8];
        *(float4*)dst       = make_float4(acc[0], acc[1], acc[2], acc[3]);
        *(float4*)(dst + 4) = make_float4(acc[4], acc[5], acc[6], acc[7]);
    }
}

// ---------------------------------------------------------------------------
// Kernel B: reduce split-K partials, fold neighbor 3x3 terms AND the root
// (joint 0) subtraction directly into W' and b'. Pads cols [151,160) to 0.
// ---------------------------------------------------------------------------
__global__ void __launch_bounds__(NKPAD)
finalize_kernel(const float* __restrict__ b_shape, const float* __restrict__ b_cam,
                const float* __restrict__ b_phi,   const float* __restrict__ b_leaf,
                const float* __restrict__ init_shape, const float* __restrict__ init_cam,
                const float* __restrict__ reg_b)
{
    GDC_LAUNCH();   // let main launch + stage X while we run
    GDC_WAIT();     // everything below reads precompute's outputs

    int row = blockIdx.x;    // 0..57
    int col = threadIdx.x;   // 0..159
    float s = 0.f;
    #pragma unroll
    for (int p = 0; p < KSPLIT; p++) s += g_Wpart[(p * 58 + row) * NKPAD + col];

    bool isPose = (col >= 79 && col < NK);
    int t = 0, j = 0, o = 0;
    float s0 = 0.f;
    if (isPose) {
        t = col - 79; j = t / 3; o = t - 3 * j;
        #pragma unroll
        for (int p = 0; p < KSPLIT; p++) s0 += g_Wpart[(p * 58 + row) * NKPAD + 79 + o];
    }

    if (row < NC) {
        float w;
        if (col >= NK) {
            w = 0.f;
        } else if (!isPose) {
            w = s;
        } else {
            w = s - s0;
            int a1 = c_NB1[j], a2 = c_NB2[j];
            if (row >= a1 && row < a1 + 3) w += g_M1[j * 9 + (row - a1) * 3 + o];
            if (row >= a2 && row < a2 + 3) w += g_M2[j * 9 + (row - a2) * 3 + o];
            // subtract joint-0 neighbor scatter (NB1[0]=51, NB2[0]=54)
            if (row >= 51 && row < 54) w -= g_M1[(row - 51) * 3 + o];
            if (row >= 54 && row < 57) w -= g_M2[(row - 54) * 3 + o];
        }
        g_W[row * NKPAD + col] = w;
    } else {
        float bv;
        if      (col >= NK) bv = 0.f;
        else if (col < 10)  bv = s + b_shape[col] + init_shape[col];
        else if (col < 13)  bv = s + b_cam[col - 10] + init_cam[col - 10];
        else if (col < 59)  bv = s + b_phi[col - 13];
        else if (col < 79)  bv = s + b_leaf[col - 59];
        else {
            float bt = s  + reg_b[t] + g_bp1[t] + g_bp2[t];
            float b0 = s0 + reg_b[o] + g_bp1[o] + g_bp2[o];
            bv = bt - b0;
        }
        g_b[col] = bv;
    }
}

// ---------------------------------------------------------------------------
// Kernel C: main — out(B,151) = x(B,57) @ W' + b'. Scalar FFMA.
// Block = 256 threads covering 64 rows x 32 cols (thread = 1 row x 8 cols).
// Results staged in smem, stored as 32-float contiguous runs (coalesced).
// grid = (B/64, 5 slices) = 640 blocks; X re-reads halved vs CPB=16.
// X staging (input-only) runs BEFORE griddepcontrol.wait -> overlaps finalize.
// ---------------------------------------------------------------------------
__global__ void __launch_bounds__(TPBM)
main_kernel(const float* __restrict__ joints, float* __restrict__ out, int B)
{
    __shared__ __align__(16) float  Xs[RPB * NC];     // 64*57*4 = 14592 B
    __shared__ __align__(16) float4 Ws4[NC][CPB / 4]; // 57*32*4 = 7296 B
    __shared__ float bias_s[CPB];
    __shared__ __align__(16) float  Os[RPB * CPB];    // 64*32*4 = 8192 B

    const int tid = threadIdx.x;
    const int rb  = blockIdx.x * RPB;
    const int k0  = blockIdx.y * CPB;

    // output section offsets (pose first, per output layout)
    const int CAM_OFF   = B * 72;
    const int PHI_OFF   = CAM_OFF + B * 3;
    const int LEAF_OFF  = PHI_OFF + B * 46;
    const int SHAPE_OFF = LEAF_OFF + B * 20;

    // ---- stage X (independent of upstream kernels -> before the wait) ----
    if (rb + RPB <= B) {
        const float4* jp = (const float4*)(joints + rb * NC);
        float4 xv[4];
        #pragma unroll
        for (int i = 0; i < 4; i++) {
            int idx = tid + TPBM * i;
            if (idx < 912) xv[i] = jp[idx];
        }
        #pragma unroll
        for (int i = 0; i < 4; i++) {
            int idx = tid + TPBM * i;
            if (idx < 912) ((float4*)Xs)[idx] = xv[i];
        }
    } else {
        int nr = B - rb;
        for (int idx = tid; idx < nr * NC; idx += TPBM)
            Xs[idx] = joints[rb * NC + idx];
    }

    GDC_WAIT();     // finalize's g_W / g_b must be complete below

    // ---- stage W slice (batched): 57 rows x 8 float4 = 456 float4 ----
    {
        float4 wv[2];
        #pragma unroll
        for (int i = 0; i < 2; i++) {
            int idx = tid + TPBM * i;
            if (idx < 456) {
                int r = idx >> 3, q = idx & 7;
                wv[i] = *(const float4*)(g_W + r * NKPAD + k0 + q * 4);
            }
        }
        #pragma unroll
        for (int i = 0; i < 2; i++) {
            int idx = tid + TPBM * i;
            if (idx < 456) {
                int r = idx >> 3, q = idx & 7;
                Ws4[r][q] = wv[i];
            }
        }
    }
    if (tid < CPB) bias_s[tid] = g_b[k0 + tid];
    __syncthreads();

    const int ty = tid >> 2;          // row within tile (0..63)
    const int cg = tid & 3;           // col group: cols cg*8 .. cg*8+7

    {
        float4 a0 = make_float4(bias_s[cg * 8 + 0], bias_s[cg * 8 + 1],
                                bias_s[cg * 8 + 2], bias_s[cg * 8 + 3]);
        float4 a1 = make_float4(bias_s[cg * 8 + 4], bias_s[cg * 8 + 5],
                                bias_s[cg * 8 + 6], bias_s[cg * 8 + 7]);

        const float* xrow = &Xs[ty * NC];
        #pragma unroll
        for (int c = 0; c < NC; c++) {
            float  xc = xrow[c];
            float4 w0 = Ws4[c][cg * 2];
            float4 w1 = Ws4[c][cg * 2 + 1];
            a0.x = fmaf(xc, w0.x, a0.x); a0.y = fmaf(xc, w0.y, a0.y);
            a0.z = fmaf(xc, w0.z, a0.z); a0.w = fmaf(xc, w0.w, a0.w);
            a1.x = fmaf(xc, w1.x, a1.x); a1.y = fmaf(xc, w1.y, a1.y);
            a1.z = fmaf(xc, w1.z, a1.z); a1.w = fmaf(xc, w1.w, a1.w);
        }

        float4* op = (float4*)&Os[ty * CPB + cg * 8];
        op[0] = a0;
        op[1] = a1;
    }
    __syncthreads();

    // ---- coalesced store: warp covers 1 row x 32 consecutive k ----
    #pragma unroll
    for (int i = 0; i < 8; i++) {
        int idx = tid + TPBM * i;         // 0..2047
        int e = idx & (CPB - 1);
        int r = idx >> 5;
        int k = k0 + e;
        int b = rb + r;
        if (k < NK && b < B) {
            float val = Os[idx];
            if      (k < 10) out[SHAPE_OFF + b * 10 + k]        = val;
            else if (k < 13) out[CAM_OFF   + b * 3  + (k - 10)] = val;
            else if (k < 59) out[PHI_OFF   + b * 46 + (k - 13)] = val;
            else if (k < 79) out[LEAF_OFF  + b * 20 + (k - 59)] = val;
            else             out[b * 72 + (k - 79)]             = val;
        }
    }
}

// ---------------------------------------------------------------------------
extern "C" void kernel_launch(void* const* d_in, const int* in_sizes, int n_in,
                              void* d_out, int out_size)
{
    const float* joints     = (const float*)d_in[0];
    const float* W_enc      = (const float*)d_in[1];
    const float* b_enc      = (const float*)d_in[2];
    const float* W_shape    = (const float*)d_in[3];
    const float* b_shape    = (const float*)d_in[4];
    const float* W_cam      = (const float*)d_in[5];
    const float* b_cam      = (const float*)d_in[6];
    const float* W_phi      = (const float*)d_in[7];
    const float* b_phi      = (const float*)d_in[8];
    const float* W_leaf     = (const float*)d_in[9];
    const float* b_leaf     = (const float*)d_in[10];
    const float* init_shape = (const float*)d_in[11];
    const float* init_cam   = (const float*)d_in[12];
    const float* L1_w       = (const float*)d_in[13];
    const float* L1_b       = (const float*)d_in[14];
    const float* L2_w       = (const float*)d_in[15];
    const float* L2_b       = (const float*)d_in[16];
    const float* Rf         = (const float*)d_in[17];
    const float* R1         = (const float*)d_in[18];
    const float* R2         = (const float*)d_in[19];
    const float* reg_b      = (const float*)d_in[20];

    int B = in_sizes[0] / NC;
    float* outf = (float*)d_out;

    // Kernel 1: normal launch
    precompute_kernel<<<5 * KSPLIT + 48, 256>>>(W_enc, b_enc, W_shape, W_cam, W_phi, W_leaf, Rf,
                                                L1_w, L1_b, L2_w, L2_b, R1, R2);

    // Kernels 2+3: programmatic dependent launch (upstream triggers at entry;
    // downstream's griddepcontrol.wait enforces full upstream completion).
    cudaLaunchAttribute pssAttr[1];
    pssAttr[0].id = cudaLaunchAttributeProgrammaticStreamSerialization;
    pssAttr[0].val.programmaticStreamSerializationAllowed = 1;

    {
        cudaLaunchConfig_t cfg = {};
        cfg.gridDim  = dim3(58);
        cfg.blockDim = dim3(NKPAD);
        cfg.attrs    = pssAttr;
        cfg.numAttrs = 1;
        cudaLaunchKernelEx(&cfg, finalize_kernel,
                           b_shape, b_cam, b_phi, b_leaf, init_shape, init_cam, reg_b);
    }
    {
        cudaLaunchConfig_t cfg = {};
        cfg.gridDim  = dim3((B + RPB - 1) / RPB, NSLICES);
        cfg.blockDim = dim3(TPBM);
        cfg.attrs    = pssAttr;
        cfg.numAttrs = 1;
        cudaLaunchKernelEx(&cfg, main_kernel, joints, outf, B);
    }
}

// round 12
// speedup vs baseline: 1.3561x; 1.3561x over previous
#include <cuda_runtime.h>

// ---------------------------------------------------------------------------
// Pose2Mesh fully-collapsed linear implementation — TWO kernels.
// Kernel 1 (fused): fold GEMM split-K partials + per-joint M dots + finalize
//   (finalize role blocks gated by a device counter; only 58 blocks spin,
//    all 426 blocks co-resident -> no deadlock; counters self-reset).
// Kernel 2: main GEMM out(B,151) = x(B,57) @ W' + b', PDL-chained.
// ---------------------------------------------------------------------------

#define D_DIM   2048
#define NC      57      // J*3
#define NK      151
#define NKPAD   160
#define KSPLIT  64
#define KCHUNK  32      // D_DIM / KSPLIT
#define H_DIM   512
#define CPB     16      // cols per block (main)
#define NSLICES 10      // 160/16
#define RPB     64      // rows per block (main)
#define TPB     128     // threads per block (main)

#define NB_FOLD 320                 // 5 * KSPLIT
#define NB_M    48
#define NB_PRE  (NB_FOLD + NB_M)    // 368
#define NB_FIN  58
#define GRID1   (NB_PRE + NB_FIN)   // 426

#define GDC_LAUNCH() asm volatile("griddepcontrol.launch_dependents;")
#define GDC_WAIT()   asm volatile("griddepcontrol.wait;" ::: "memory")

// scratch (allocation-free: __device__ globals)
__device__ float g_M1[24 * 9];
__device__ float g_M2[24 * 9];
__device__ float g_bp1[72];
__device__ float g_bp2[72];
__device__ float g_Wpart[KSPLIT * 58 * NKPAD];
__device__ float g_W[NC * NKPAD];
__device__ float g_b[NKPAD];

// phase counters (zero at load; self-reset each launch -> graph-replay safe)
__device__ int g_c1;     // producer blocks done (target NB_PRE)
__device__ int g_done;   // kernel-1 blocks retired (target GRID1)

// NEB1[j]*3 and NEB2[j]*3 (base offsets into the 57-float joint vector)
__constant__ int c_NB1[24] = {51,33,36,51,39,42,51,45,48,54,45,48,54,54,54,54,15,18,21,24,27,30,27,30};
__constant__ int c_NB2[24] = {54,51,51,54,33,36,54,39,42,51,39,42, 0,15,18, 0,54,54,15,18,21,24,21,24};

__device__ __forceinline__ float fetchB(int f, int col,
                                        const float* __restrict__ Wsh, const float* __restrict__ Wca,
                                        const float* __restrict__ Wph, const float* __restrict__ Wlf,
                                        const float* __restrict__ Rf)
{
    if (col < 10)  return Wsh[f * 10 + col];
    if (col < 13)  return Wca[f * 3  + (col - 10)];
    if (col < 59)  return Wph[f * 46 + (col - 13)];
    if (col < 79)  return Wlf[f * 20 + (col - 59)];
    int t = col - 79;
    int j = t / 3, o = t - j * 3;
    return Rf[(j * D_DIM + f) * 3 + o];
}

__device__ __forceinline__ void spin_ge(volatile int* p, int target) {
    while (*p < target) __nanosleep(128);
}

// ---------------------------------------------------------------------------
// Kernel 1: fold + M-part + finalize (counter-gated)
// ---------------------------------------------------------------------------
__global__ void __launch_bounds__(256)
precompute_finalize_kernel(const float* __restrict__ W_enc, const float* __restrict__ b_enc,
                           const float* __restrict__ W_shape, const float* __restrict__ W_cam,
                           const float* __restrict__ W_phi,   const float* __restrict__ W_leaf,
                           const float* __restrict__ Rf,
                           const float* __restrict__ L1_w, const float* __restrict__ L1_b,
                           const float* __restrict__ L2_w, const float* __restrict__ L2_b,
                           const float* __restrict__ R1,   const float* __restrict__ R2,
                           const float* __restrict__ b_shape, const float* __restrict__ b_cam,
                           const float* __restrict__ b_phi,   const float* __restrict__ b_leaf,
                           const float* __restrict__ init_shape, const float* __restrict__ init_cam,
                           const float* __restrict__ reg_b)
{
    GDC_LAUNCH();   // let main launch + stage X while we run

    int bx  = blockIdx.x;
    int tid = threadIdx.x;

    if (bx < NB_FOLD) {
        // ================= fold GEMM: K=32 chunk per block, split-K partials
        __shared__ float As[64][KCHUNK + 1];
        __shared__ __align__(16) float Bs[KCHUNK][36];

        int ct = bx % 5;
        int ks = bx / 5;
        int kbase = ks * KCHUNK;

        float4 va[2];
        int    vr[2], vq[2];
        #pragma unroll
        for (int i = 0; i < 2; i++) {
            int idx = tid + 256 * i;
            int r = idx >> 3, q = idx & 7;
            vr[i] = r; vq[i] = q;
            float4 v4 = make_float4(0.f, 0.f, 0.f, 0.f);
            if (r < NC)       v4 = *(const float4*)(W_enc + r * D_DIM + kbase + q * 4);
            else if (r == NC) v4 = *(const float4*)(b_enc + kbase + q * 4);
            va[i] = v4;
        }
        float vb[4];
        #pragma unroll
        for (int i = 0; i < 4; i++) {
            int idx = tid + 256 * i;
            int kk = idx >> 5, cl = idx & 31;
            int gcol = ct * 32 + cl;
            vb[i] = (gcol < NK) ? fetchB(kbase + kk, gcol, W_shape, W_cam, W_phi, W_leaf, Rf) : 0.f;
        }
        #pragma unroll
        for (int i = 0; i < 2; i++) {
            if (vr[i] < 64) {
                float* dst = &As[vr[i]][vq[i] * 4];
                dst[0] = va[i].x; dst[1] = va[i].y; dst[2] = va[i].z; dst[3] = va[i].w;
            }
        }
        #pragma unroll
        for (int i = 0; i < 4; i++) {
            int idx = tid + 256 * i;
            Bs[idx >> 5][idx & 31] = vb[i];
        }
        __syncthreads();

        int r  = tid >> 2;
        int cg = tid & 3;
        float acc[8];
        #pragma unroll
        for (int e = 0; e < 8; e++) acc[e] = 0.f;
        #pragma unroll
        for (int kk = 0; kk < KCHUNK; kk++) {
            float  xc = As[r][kk];
            float4 w0 = *(const float4*)&Bs[kk][cg * 8];
            float4 w1 = *(const float4*)&Bs[kk][cg * 8 + 4];
            acc[0] = fmaf(xc, w0.x, acc[0]); acc[1] = fmaf(xc, w0.y, acc[1]);
            acc[2] = fmaf(xc, w0.z, acc[2]); acc[3] = fmaf(xc, w0.w, acc[3]);
            acc[4] = fmaf(xc, w1.x, acc[4]); acc[5] = fmaf(xc, w1.y, acc[5]);
            acc[6] = fmaf(xc, w1.z, acc[6]); acc[7] = fmaf(xc, w1.w, acc[7]);
        }
        if (r < 58) {
            float* dst = &g_Wpart[(ks * 58 + r) * NKPAD + ct * 32 + cg * 8];
            *(float4*)dst       = make_float4(acc[0], acc[1], acc[2], acc[3]);
            *(float4*)(dst + 4) = make_float4(acc[4], acc[5], acc[6], acc[7]);
        }
        __syncthreads();
        __threadfence();
        if (tid == 0) atomicAdd(&g_c1, 1);
    }
    else if (bx < NB_PRE) {
        // ================= M-part: per-(joint, side) dots from smem
        __shared__ __align__(16) float sLw[3 * H_DIM];
        __shared__ __align__(16) float sR [H_DIM * 3];
        __shared__ __align__(16) float sLb[H_DIM];

        int mb = bx - NB_FOLD;            // 0..47
        int j  = mb >> 1;
        int s  = mb & 1;
        const float* Lw = (s ? L2_w : L1_w) + j * 3 * H_DIM;
        const float* Lb = (s ? L2_b : L1_b) + j * H_DIM;
        const float* Rm = (s ? R2   : R1  ) + j * H_DIM * 3;

        float4 v[4];
        #pragma unroll
        for (int i = 0; i < 4; i++) {
            int idx = tid + 256 * i;
            if      (idx < 384) v[i] = *(const float4*)(Lw + idx * 4);
            else if (idx < 768) v[i] = *(const float4*)(Rm + (idx - 384) * 4);
            else if (idx < 896) v[i] = *(const float4*)(Lb + (idx - 768) * 4);
        }
        #pragma unroll
        for (int i = 0; i < 4; i++) {
            int idx = tid + 256 * i;
            if      (idx < 384) *(float4*)(sLw + idx * 4)         = v[i];
            else if (idx < 768) *(float4*)(sR  + (idx - 384) * 4) = v[i];
            else if (idx < 896) *(float4*)(sLb + (idx - 768) * 4) = v[i];
        }
        __syncthreads();

        int lane = tid & 31;
        int w    = tid >> 5;              // 0..7
        for (int t = w; t < 12; t += 8) {
            int c = (t < 9) ? (t / 3) : 0;
            int o = (t < 9) ? (t % 3) : (t - 9);
            const float* ap = (t < 9) ? (sLw + c * H_DIM) : sLb;
            float sum = 0.f;
            #pragma unroll
            for (int i = 0; i < 16; i++) {
                int h = lane + 32 * i;
                sum = fmaf(ap[h], sR[h * 3 + o], sum);
            }
            #pragma unroll
            for (int d = 16; d > 0; d >>= 1) sum += __shfl_xor_sync(0xffffffffu, sum, d);
            if (lane == 0) {
                if (t < 9) { if (s) g_M2[j * 9 + t] = sum; else g_M1[j * 9 + t] = sum; }
                else       { if (s) g_bp2[j * 3 + o] = sum; else g_bp1[j * 3 + o] = sum; }
            }
        }
        __syncthreads();
        __threadfence();
        if (tid == 0) atomicAdd(&g_c1, 1);
    }
    else {
        // ================= finalize (58 blocks, gated on producers)
        if (tid == 0) spin_ge(&g_c1, NB_PRE);
        __syncthreads();
        __threadfence();

        int row = bx - NB_PRE;            // 0..57
        int col = tid;                    // threads 160..255 idle
        if (col < NKPAD) {
            float s = 0.f;
            #pragma unroll
            for (int p = 0; p < KSPLIT; p++) s += g_Wpart[(p * 58 + row) * NKPAD + col];

            bool isPose = (col >= 79 && col < NK);
            int t = 0, j = 0, o = 0;
            float s0 = 0.f;
            if (isPose) {
                t = col - 79; j = t / 3; o = t - 3 * j;
                #pragma unroll
                for (int p = 0; p < KSPLIT; p++) s0 += g_Wpart[(p * 58 + row) * NKPAD + 79 + o];
            }

            if (row < NC) {
                float w;
                if (col >= NK) {
                    w = 0.f;
                } else if (!isPose) {
                    w = s;
                } else {
                    w = s - s0;
                    int a1 = c_NB1[j], a2 = c_NB2[j];
                    if (row >= a1 && row < a1 + 3) w += g_M1[j * 9 + (row - a1) * 3 + o];
                    if (row >= a2 && row < a2 + 3) w += g_M2[j * 9 + (row - a2) * 3 + o];
                    // subtract joint-0 neighbor scatter (NB1[0]=51, NB2[0]=54)
                    if (row >= 51 && row < 54) w -= g_M1[(row - 51) * 3 + o];
                    if (row >= 54 && row < 57) w -= g_M2[(row - 54) * 3 + o];
                }
                g_W[row * NKPAD + col] = w;
            } else {
                float bv;
                if      (col >= NK) bv = 0.f;
                else if (col < 10)  bv = s + b_shape[col] + init_shape[col];
                else if (col < 13)  bv = s + b_cam[col - 10] + init_cam[col - 10];
                else if (col < 59)  bv = s + b_phi[col - 13];
                else if (col < 79)  bv = s + b_leaf[col - 59];
                else {
                    float bt = s  + reg_b[t] + g_bp1[t] + g_bp2[t];
                    float b0 = s0 + reg_b[o] + g_bp1[o] + g_bp2[o];
                    bv = bt - b0;
                }
                g_b[col] = bv;
            }
        }
    }

    // ---- last-block-out counter reset (graph-replay safe) ----
    __threadfence();
    if (tid == 0) {
        int old = atomicAdd(&g_done, 1);
        if (old == GRID1 - 1) {
            g_c1 = 0;
            __threadfence();
            g_done = 0;
        }
    }
}

// ---------------------------------------------------------------------------
// Kernel 2: main — out(B,151) = x(B,57) @ W' + b'. Scalar FFMA.
// Block = 128 threads covering 64 rows x 16 cols; results staged in smem,
// stored as 16-float contiguous runs (coalesced). grid = (B/64, 10 slices).
// X staging (input-only) runs BEFORE griddepcontrol.wait -> overlaps kernel 1.
// ---------------------------------------------------------------------------
__global__ void __launch_bounds__(TPB)
main_kernel(const float* __restrict__ joints, float* __restrict__ out, int B)
{
    __shared__ __align__(16) float  Xs[RPB * NC];     // 64*57*4 = 14592 B
    __shared__ __align__(16) float4 Ws4[NC][CPB / 4]; // 57*16*4 = 3648 B
    __shared__ float bias_s[CPB];
    __shared__ __align__(16) float  Os[RPB * CPB];    // 64*16*4 = 4096 B

    const int tid = threadIdx.x;
    const int rb  = blockIdx.x * RPB;
    const int k0  = blockIdx.y * CPB;

    // output section offsets (pose first, per output layout)
    const int CAM_OFF   = B * 72;
    const int PHI_OFF   = CAM_OFF + B * 3;
    const int LEAF_OFF  = PHI_OFF + B * 46;
    const int SHAPE_OFF = LEAF_OFF + B * 20;

    // ---- stage X (independent of upstream kernel -> before the wait) ----
    if (rb + RPB <= B) {
        const float4* jp = (const float4*)(joints + rb * NC);
        float4 xv[8];
        #pragma unroll
        for (int i = 0; i < 8; i++) {
            int idx = tid + TPB * i;
            if (idx < 912) xv[i] = jp[idx];
        }
        #pragma unroll
        for (int i = 0; i < 8; i++) {
            int idx = tid + TPB * i;
            if (idx < 912) ((float4*)Xs)[idx] = xv[i];
        }
    } else {
        int nr = B - rb;
        for (int idx = tid; idx < nr * NC; idx += TPB)
            Xs[idx] = joints[rb * NC + idx];
    }

    GDC_WAIT();     // kernel 1's g_W / g_b must be complete below

    // ---- stage W slice (batched): 57 rows x 4 float4 = 228 float4 ----
    {
        float4 wv[2];
        #pragma unroll
        for (int i = 0; i < 2; i++) {
            int idx = tid + TPB * i;
            if (idx < 228) {
                int r = idx >> 2, q = idx & 3;
                wv[i] = *(const float4*)(g_W + r * NKPAD + k0 + q * 4);
            }
        }
        #pragma unroll
        for (int i = 0; i < 2; i++) {
            int idx = tid + TPB * i;
            if (idx < 228) {
                int r = idx >> 2, q = idx & 3;
                Ws4[r][q] = wv[i];
            }
        }
    }
    if (tid < CPB) bias_s[tid] = g_b[k0 + tid];
    __syncthreads();

    const int ty = tid >> 1;          // row within tile (0..63)
    const int tx = tid & 1;           // column half (0/1)

    {
        float4 a0 = make_float4(bias_s[tx * 8 + 0], bias_s[tx * 8 + 1],
                                bias_s[tx * 8 + 2], bias_s[tx * 8 + 3]);
        float4 a1 = make_float4(bias_s[tx * 8 + 4], bias_s[tx * 8 + 5],
                                bias_s[tx * 8 + 6], bias_s[tx * 8 + 7]);

        const float* xrow = &Xs[ty * NC];
        #pragma unroll
        for (int c = 0; c < NC; c++) {
            float  xc = xrow[c];
            float4 w0 = Ws4[c][tx * 2];
            float4 w1 = Ws4[c][tx * 2 + 1];
            a0.x = fmaf(xc, w0.x, a0.x); a0.y = fmaf(xc, w0.y, a0.y);
            a0.z = fmaf(xc, w0.z, a0.z); a0.w = fmaf(xc, w0.w, a0.w);
            a1.x = fmaf(xc, w1.x, a1.x); a1.y = fmaf(xc, w1.y, a1.y);
            a1.z = fmaf(xc, w1.z, a1.z); a1.w = fmaf(xc, w1.w, a1.w);
        }

        float4* op = (float4*)&Os[ty * CPB + tx * 8];
        op[0] = a0;
        op[1] = a1;
    }
    __syncthreads();

    // ---- coalesced store: warp covers 2 rows x 16 consecutive k ----
    #pragma unroll
    for (int i = 0; i < 8; i++) {
        int idx = tid + TPB * i;          // 0..1023
        int e = idx & (CPB - 1);
        int r = idx >> 4;
        int k = k0 + e;
        int b = rb + r;
        if (k < NK && b < B) {
            float val = Os[idx];
            if      (k < 10) out[SHAPE_OFF + b * 10 + k]        = val;
            else if (k < 13) out[CAM_OFF   + b * 3  + (k - 10)] = val;
            else if (k < 59) out[PHI_OFF   + b * 46 + (k - 13)] = val;
            else if (k < 79) out[LEAF_OFF  + b * 20 + (k - 59)] = val;
            else             out[b * 72 + (k - 79)]             = val;
        }
    }
}

// ---------------------------------------------------------------------------
extern "C" void kernel_launch(void* const* d_in, const int* in_sizes, int n_in,
                              void* d_out, int out_size)
{
    const float* joints     = (const float*)d_in[0];
    const float* W_enc      = (const float*)d_in[1];
    const float* b_enc      = (const float*)d_in[2];
    const float* W_shape    = (const float*)d_in[3];
    const float* b_shape    = (const float*)d_in[4];
    const float* W_cam      = (const float*)d_in[5];
    const float* b_cam      = (const float*)d_in[6];
    const float* W_phi      = (const float*)d_in[7];
    const float* b_phi      = (const float*)d_in[8];
    const float* W_leaf     = (const float*)d_in[9];
    const float* b_leaf     = (const float*)d_in[10];
    const float* init_shape = (const float*)d_in[11];
    const float* init_cam   = (const float*)d_in[12];
    const float* L1_w       = (const float*)d_in[13];
    const float* L1_b       = (const float*)d_in[14];
    const float* L2_w       = (const float*)d_in[15];
    const float* L2_b       = (const float*)d_in[16];
    const float* Rf         = (const float*)d_in[17];
    const float* R1         = (const float*)d_in[18];
    const float* R2         = (const float*)d_in[19];
    const float* reg_b      = (const float*)d_in[20];

    int B = in_sizes[0] / NC;
    float* outf = (float*)d_out;

    // Kernel 1: fused precompute + finalize
    precompute_finalize_kernel<<<GRID1, 256>>>(W_enc, b_enc, W_shape, W_cam, W_phi, W_leaf, Rf,
                                               L1_w, L1_b, L2_w, L2_b, R1, R2,
                                               b_shape, b_cam, b_phi, b_leaf,
                                               init_shape, init_cam, reg_b);

    // Kernel 2: programmatic dependent launch (upstream triggers at entry;
    // downstream's griddepcontrol.wait enforces full upstream completion).
    cudaLaunchAttribute pssAttr[1];
    pssAttr[0].id = cudaLaunchAttributeProgrammaticStreamSerialization;
    pssAttr[0].val.programmaticStreamSerializationAllowed = 1;

    cudaLaunchConfig_t cfg = {};
    cfg.gridDim  = dim3((B + RPB - 1) / RPB, NSLICES);
    cfg.blockDim = dim3(TPB);
    cfg.attrs    = pssAttr;
    cfg.numAttrs = 1;
    cudaLaunchKernelEx(&cfg, main_kernel, joints, outf, B);
}

// round 13
// speedup vs baseline: 1.3810x; 1.0184x over previous
#include <cuda_runtime.h>

// ---------------------------------------------------------------------------
// Pose2Mesh fully-collapsed linear implementation — TWO kernels.
// Kernel 1 (fused): fold GEMM split-K partials + per-joint M dots + finalize
//   (finalize role blocks gated by a device counter; only 58 blocks spin,
//    all 426 blocks co-resident -> no deadlock; counters self-reset).
// Kernel 2: main GEMM out(B,151) = x(B,57) @ W' + b', PDL-chained.
//   Compute layout: thread = 2 rows x 8 cols (weight LDS.128 shared across
//   both rows -> half the smem-crossbar wavefronts per FMA).
// ---------------------------------------------------------------------------

#define D_DIM   2048
#define NC      57      // J*3
#define NK      151
#define NKPAD   160
#define KSPLIT  64
#define KCHUNK  32      // D_DIM / KSPLIT
#define H_DIM   512
#define CPB     16      // cols per block (main)
#define NSLICES 10      // 160/16
#define RPB     64      // rows per block (main)
#define TPB     128     // threads per block (main)

#define NB_FOLD 320                 // 5 * KSPLIT
#define NB_M    48
#define NB_PRE  (NB_FOLD + NB_M)    // 368
#define NB_FIN  58
#define GRID1   (NB_PRE + NB_FIN)   // 426

#define GDC_LAUNCH() asm volatile("griddepcontrol.launch_dependents;")
#define GDC_WAIT()   asm volatile("griddepcontrol.wait;" ::: "memory")

// scratch (allocation-free: __device__ globals)
__device__ float g_M1[24 * 9];
__device__ float g_M2[24 * 9];
__device__ float g_bp1[72];
__device__ float g_bp2[72];
__device__ float g_Wpart[KSPLIT * 58 * NKPAD];
__device__ float g_W[NC * NKPAD];
__device__ float g_b[NKPAD];

// phase counters (zero at load; self-reset each launch -> graph-replay safe)
__device__ int g_c1;     // producer blocks done (target NB_PRE)
__device__ int g_done;   // kernel-1 blocks retired (target GRID1)

// NEB1[j]*3 and NEB2[j]*3 (base offsets into the 57-float joint vector)
__constant__ int c_NB1[24] = {51,33,36,51,39,42,51,45,48,54,45,48,54,54,54,54,15,18,21,24,27,30,27,30};
__constant__ int c_NB2[24] = {54,51,51,54,33,36,54,39,42,51,39,42, 0,15,18, 0,54,54,15,18,21,24,21,24};

__device__ __forceinline__ float fetchB(int f, int col,
                                        const float* __restrict__ Wsh, const float* __restrict__ Wca,
                                        const float* __restrict__ Wph, const float* __restrict__ Wlf,
                                        const float* __restrict__ Rf)
{
    if (col < 10)  return Wsh[f * 10 + col];
    if (col < 13)  return Wca[f * 3  + (col - 10)];
    if (col < 59)  return Wph[f * 46 + (col - 13)];
    if (col < 79)  return Wlf[f * 20 + (col - 59)];
    int t = col - 79;
    int j = t / 3, o = t - j * 3;
    return Rf[(j * D_DIM + f) * 3 + o];
}

__device__ __forceinline__ void spin_ge(volatile int* p, int target) {
    while (*p < target) __nanosleep(128);
}

// ---------------------------------------------------------------------------
// Kernel 1: fold + M-part + finalize (counter-gated)
// ---------------------------------------------------------------------------
__global__ void __launch_bounds__(256)
precompute_finalize_kernel(const float* __restrict__ W_enc, const float* __restrict__ b_enc,
                           const float* __restrict__ W_shape, const float* __restrict__ W_cam,
                           const float* __restrict__ W_phi,   const float* __restrict__ W_leaf,
                           const float* __restrict__ Rf,
                           const float* __restrict__ L1_w, const float* __restrict__ L1_b,
                           const float* __restrict__ L2_w, const float* __restrict__ L2_b,
                           const float* __restrict__ R1,   const float* __restrict__ R2,
                           const float* __restrict__ b_shape, const float* __restrict__ b_cam,
                           const float* __restrict__ b_phi,   const float* __restrict__ b_leaf,
                           const float* __restrict__ init_shape, const float* __restrict__ init_cam,
                           const float* __restrict__ reg_b)
{
    GDC_LAUNCH();   // let main launch + stage X while we run

    int bx  = blockIdx.x;
    int tid = threadIdx.x;

    if (bx < NB_FOLD) {
        // ================= fold GEMM: K=32 chunk per block, split-K partials
        __shared__ float As[64][KCHUNK + 1];
        __shared__ __align__(16) float Bs[KCHUNK][36];

        int ct = bx % 5;
        int ks = bx / 5;
        int kbase = ks * KCHUNK;

        float4 va[2];
        int    vr[2], vq[2];
        #pragma unroll
        for (int i = 0; i < 2; i++) {
            int idx = tid + 256 * i;
            int r = idx >> 3, q = idx & 7;
            vr[i] = r; vq[i] = q;
            float4 v4 = make_float4(0.f, 0.f, 0.f, 0.f);
            if (r < NC)       v4 = *(const float4*)(W_enc + r * D_DIM + kbase + q * 4);
            else if (r == NC) v4 = *(const float4*)(b_enc + kbase + q * 4);
            va[i] = v4;
        }
        float vb[4];
        #pragma unroll
        for (int i = 0; i < 4; i++) {
            int idx = tid + 256 * i;
            int kk = idx >> 5, cl = idx & 31;
            int gcol = ct * 32 + cl;
            vb[i] = (gcol < NK) ? fetchB(kbase + kk, gcol, W_shape, W_cam, W_phi, W_leaf, Rf) : 0.f;
        }
        #pragma unroll
        for (int i = 0; i < 2; i++) {
            if (vr[i] < 64) {
                float* dst = &As[vr[i]][vq[i] * 4];
                dst[0] = va[i].x; dst[1] = va[i].y; dst[2] = va[i].z; dst[3] = va[i].w;
            }
        }
        #pragma unroll
        for (int i = 0; i < 4; i++) {
            int idx = tid + 256 * i;
            Bs[idx >> 5][idx & 31] = vb[i];
        }
        __syncthreads();

        int r  = tid >> 2;
        int cg = tid & 3;
        float acc[8];
        #pragma unroll
        for (int e = 0; e < 8; e++) acc[e] = 0.f;
        #pragma unroll
        for (int kk = 0; kk < KCHUNK; kk++) {
            float  xc = As[r][kk];
            float4 w0 = *(const float4*)&Bs[kk][cg * 8];
            float4 w1 = *(const float4*)&Bs[kk][cg * 8 + 4];
            acc[0] = fmaf(xc, w0.x, acc[0]); acc[1] = fmaf(xc, w0.y, acc[1]);
            acc[2] = fmaf(xc, w0.z, acc[2]); acc[3] = fmaf(xc, w0.w, acc[3]);
            acc[4] = fmaf(xc, w1.x, acc[4]); acc[5] = fmaf(xc, w1.y, acc[5]);
            acc[6] = fmaf(xc, w1.z, acc[6]); acc[7] = fmaf(xc, w1.w, acc[7]);
        }
        if (r < 58) {
            float* dst = &g_Wpart[(ks * 58 + r) * NKPAD + ct * 32 + cg * 8];
            *(float4*)dst       = make_float4(acc[0], acc[1], acc[2], acc[3]);
            *(float4*)(dst + 4) = make_float4(acc[4], acc[5], acc[6], acc[7]);
        }
        __syncthreads();
        __threadfence();
        if (tid == 0) atomicAdd(&g_c1, 1);
    }
    else if (bx < NB_PRE) {
        // ================= M-part: per-(joint, side) dots from smem
        __shared__ __align__(16) float sLw[3 * H_DIM];
        __shared__ __align__(16) float sR [H_DIM * 3];
        __shared__ __align__(16) float sLb[H_DIM];

        int mb = bx - NB_FOLD;            // 0..47
        int j  = mb >> 1;
        int s  = mb & 1;
        const float* Lw = (s ? L2_w : L1_w) + j * 3 * H_DIM;
        const float* Lb = (s ? L2_b : L1_b) + j * H_DIM;
        const float* Rm = (s ? R2   : R1  ) + j * H_DIM * 3;

        float4 v[4];
        #pragma unroll
        for (int i = 0; i < 4; i++) {
            int idx = tid + 256 * i;
            if      (idx < 384) v[i] = *(const float4*)(Lw + idx * 4);
            else if (idx < 768) v[i] = *(const float4*)(Rm + (idx - 384) * 4);
            else if (idx < 896) v[i] = *(const float4*)(Lb + (idx - 768) * 4);
        }
        #pragma unroll
        for (int i = 0; i < 4; i++) {
            int idx = tid + 256 * i;
            if      (idx < 384) *(float4*)(sLw + idx * 4)         = v[i];
            else if (idx < 768) *(float4*)(sR  + (idx - 384) * 4) = v[i];
            else if (idx < 896) *(float4*)(sLb + (idx - 768) * 4) = v[i];
        }
        __syncthreads();

        int lane = tid & 31;
        int w    = tid >> 5;              // 0..7
        for (int t = w; t < 12; t += 8) {
            int c = (t < 9) ? (t / 3) : 0;
            int o = (t < 9) ? (t % 3) : (t - 9);
            const float* ap = (t < 9) ? (sLw + c * H_DIM) : sLb;
            float sum = 0.f;
            #pragma unroll
            for (int i = 0; i < 16; i++) {
                int h = lane + 32 * i;
                sum = fmaf(ap[h], sR[h * 3 + o], sum);
            }
            #pragma unroll
            for (int d = 16; d > 0; d >>= 1) sum += __shfl_xor_sync(0xffffffffu, sum, d);
            if (lane == 0) {
                if (t < 9) { if (s) g_M2[j * 9 + t] = sum; else g_M1[j * 9 + t] = sum; }
                else       { if (s) g_bp2[j * 3 + o] = sum; else g_bp1[j * 3 + o] = sum; }
            }
        }
        __syncthreads();
        __threadfence();
        if (tid == 0) atomicAdd(&g_c1, 1);
    }
    else {
        // ================= finalize (58 blocks, gated on producers)
        if (tid == 0) spin_ge(&g_c1, NB_PRE);
        __syncthreads();
        __threadfence();

        int row = bx - NB_PRE;            // 0..57
        int col = tid;                    // threads 160..255 idle
        if (col < NKPAD) {
            float s = 0.f;
            #pragma unroll
            for (int p = 0; p < KSPLIT; p++) s += g_Wpart[(p * 58 + row) * NKPAD + col];

            bool isPose = (col >= 79 && col < NK);
            int t = 0, j = 0, o = 0;
            float s0 = 0.f;
            if (isPose) {
                t = col - 79; j = t / 3; o = t - 3 * j;
                #pragma unroll
                for (int p = 0; p < KSPLIT; p++) s0 += g_Wpart[(p * 58 + row) * NKPAD + 79 + o];
            }

            if (row < NC) {
                float w;
                if (col >= NK) {
                    w = 0.f;
                } else if (!isPose) {
                    w = s;
                } else {
                    w = s - s0;
                    int a1 = c_NB1[j], a2 = c_NB2[j];
                    if (row >= a1 && row < a1 + 3) w += g_M1[j * 9 + (row - a1) * 3 + o];
                    if (row >= a2 && row < a2 + 3) w += g_M2[j * 9 + (row - a2) * 3 + o];
                    // subtract joint-0 neighbor scatter (NB1[0]=51, NB2[0]=54)
                    if (row >= 51 && row < 54) w -= g_M1[(row - 51) * 3 + o];
                    if (row >= 54 && row < 57) w -= g_M2[(row - 54) * 3 + o];
                }
                g_W[row * NKPAD + col] = w;
            } else {
                float bv;
                if      (col >= NK) bv = 0.f;
                else if (col < 10)  bv = s + b_shape[col] + init_shape[col];
                else if (col < 13)  bv = s + b_cam[col - 10] + init_cam[col - 10];
                else if (col < 59)  bv = s + b_phi[col - 13];
                else if (col < 79)  bv = s + b_leaf[col - 59];
                else {
                    float bt = s  + reg_b[t] + g_bp1[t] + g_bp2[t];
                    float b0 = s0 + reg_b[o] + g_bp1[o] + g_bp2[o];
                    bv = bt - b0;
                }
                g_b[col] = bv;
            }
        }
    }

    // ---- last-block-out counter reset (graph-replay safe) ----
    __threadfence();
    if (tid == 0) {
        int old = atomicAdd(&g_done, 1);
        if (old == GRID1 - 1) {
            g_c1 = 0;
            __threadfence();
            g_done = 0;
        }
    }
}

// ---------------------------------------------------------------------------
// Kernel 2: main — out(B,151) = x(B,57) @ W' + b'. Scalar FFMA.
// Staging + stores use all 128 threads; compute uses threads 0..63, each
// handling 2 rows x 8 cols (weight loads amortized over both rows).
// grid = (B/64, 10 slices) = 1280 blocks.
// X staging (input-only) runs BEFORE griddepcontrol.wait -> overlaps kernel 1.
// ---------------------------------------------------------------------------
__global__ void __launch_bounds__(TPB)
main_kernel(const float* __restrict__ joints, float* __restrict__ out, int B)
{
    __shared__ __align__(16) float  Xs[RPB * NC];     // 64*57*4 = 14592 B
    __shared__ __align__(16) float4 Ws4[NC][CPB / 4]; // 57*16*4 = 3648 B
    __shared__ float bias_s[CPB];
    __shared__ __align__(16) float  Os[RPB * CPB];    // 64*16*4 = 4096 B

    const int tid = threadIdx.x;
    const int rb  = blockIdx.x * RPB;
    const int k0  = blockIdx.y * CPB;

    // output section offsets (pose first, per output layout)
    const int CAM_OFF   = B * 72;
    const int PHI_OFF   = CAM_OFF + B * 3;
    const int LEAF_OFF  = PHI_OFF + B * 46;
    const int SHAPE_OFF = LEAF_OFF + B * 20;

    // ---- stage X (independent of upstream kernel -> before the wait) ----
    if (rb + RPB <= B) {
        const float4* jp = (const float4*)(joints + rb * NC);
        float4 xv[8];
        #pragma unroll
        for (int i = 0; i < 8; i++) {
            int idx = tid + TPB * i;
            if (idx < 912) xv[i] = jp[idx];
        }
        #pragma unroll
        for (int i = 0; i < 8; i++) {
            int idx = tid + TPB * i;
            if (idx < 912) ((float4*)Xs)[idx] = xv[i];
        }
    } else {
        int nr = B - rb;
        for (int idx = tid; idx < nr * NC; idx += TPB)
            Xs[idx] = joints[rb * NC + idx];
    }

    GDC_WAIT();     // kernel 1's g_W / g_b must be complete below

    // ---- stage W slice (batched): 57 rows x 4 float4 = 228 float4 ----
    {
        float4 wv[2];
        #pragma unroll
        for (int i = 0; i < 2; i++) {
            int idx = tid + TPB * i;
            if (idx < 228) {
                int r = idx >> 2, q = idx & 3;
                wv[i] = *(const float4*)(g_W + r * NKPAD + k0 + q * 4);
            }
        }
        #pragma unroll
        for (int i = 0; i < 2; i++) {
            int idx = tid + TPB * i;
            if (idx < 228) {
                int r = idx >> 2, q = idx & 3;
                Ws4[r][q] = wv[i];
            }
        }
    }
    if (tid < CPB) bias_s[tid] = g_b[k0 + tid];
    __syncthreads();

    // ---- compute: threads 0..63, each 2 rows x 8 cols ----
    if (tid < 64) {
        const int ty = tid >> 1;          // 0..31 -> rows 2ty, 2ty+1
        const int tx = tid & 1;           // column half (0/1)
        const int r0 = 2 * ty, r1 = r0 + 1;

        float4 a0 = make_float4(bias_s[tx * 8 + 0], bias_s[tx * 8 + 1],
                                bias_s[tx * 8 + 2], bias_s[tx * 8 + 3]);
        float4 a1 = make_float4(bias_s[tx * 8 + 4], bias_s[tx * 8 + 5],
                                bias_s[tx * 8 + 6], bias_s[tx * 8 + 7]);
        float4 b0 = a0;
        float4 b1 = a1;

        const float* x0 = &Xs[r0 * NC];
        const float* x1 = &Xs[r1 * NC];
        #pragma unroll
        for (int c = 0; c < NC; c++) {
            float  xa = x0[c];
            float  xb = x1[c];
            float4 w0 = Ws4[c][tx * 2];
            float4 w1 = Ws4[c][tx * 2 + 1];
            a0.x = fmaf(xa, w0.x, a0.x); a0.y = fmaf(xa, w0.y, a0.y);
            a0.z = fmaf(xa, w0.z, a0.z); a0.w = fmaf(xa, w0.w, a0.w);
            a1.x = fmaf(xa, w1.x, a1.x); a1.y = fmaf(xa, w1.y, a1.y);
            a1.z = fmaf(xa, w1.z, a1.z); a1.w = fmaf(xa, w1.w, a1.w);
            b0.x = fmaf(xb, w0.x, b0.x); b0.y = fmaf(xb, w0.y, b0.y);
            b0.z = fmaf(xb, w0.z, b0.z); b0.w = fmaf(xb, w0.w, b0.w);
            b1.x = fmaf(xb, w1.x, b1.x); b1.y = fmaf(xb, w1.y, b1.y);
            b1.z = fmaf(xb, w1.z, b1.z); b1.w = fmaf(xb, w1.w, b1.w);
        }

        float4* op0 = (float4*)&Os[r0 * CPB + tx * 8];
        op0[0] = a0;
        op0[1] = a1;
        float4* op1 = (float4*)&Os[r1 * CPB + tx * 8];
        op1[0] = b0;
        op1[1] = b1;
    }
    __syncthreads();

    // ---- coalesced store: warp covers 2 rows x 16 consecutive k ----
    #pragma unroll
    for (int i = 0; i < 8; i++) {
        int idx = tid + TPB * i;          // 0..1023
        int e = idx & (CPB - 1);
        int r = idx >> 4;
        int k = k0 + e;
        int b = rb + r;
        if (k < NK && b < B) {
            float val = Os[idx];
            if      (k < 10) out[SHAPE_OFF + b * 10 + k]        = val;
            else if (k < 13) out[CAM_OFF   + b * 3  + (k - 10)] = val;
            else if (k < 59) out[PHI_OFF   + b * 46 + (k - 13)] = val;
            else if (k < 79) out[LEAF_OFF  + b * 20 + (k - 59)] = val;
            else             out[b * 72 + (k - 79)]             = val;
        }
    }
}

// ---------------------------------------------------------------------------
extern "C" void kernel_launch(void* const* d_in, const int* in_sizes, int n_in,
                              void* d_out, int out_size)
{
    const float* joints     = (const float*)d_in[0];
    const float* W_enc      = (const float*)d_in[1];
    const float* b_enc      = (const float*)d_in[2];
    const float* W_shape    = (const float*)d_in[3];
    const float* b_shape    = (const float*)d_in[4];
    const float* W_cam      = (const float*)d_in[5];
    const float* b_cam      = (const float*)d_in[6];
    const float* W_phi      = (const float*)d_in[7];
    const float* b_phi      = (const float*)d_in[8];
    const float* W_leaf     = (const float*)d_in[9];
    const float* b_leaf     = (const float*)d_in[10];
    const float* init_shape = (const float*)d_in[11];
    const float* init_cam   = (const float*)d_in[12];
    const float* L1_w       = (const float*)d_in[13];
    const float* L1_b       = (const float*)d_in[14];
    const float* L2_w       = (const float*)d_in[15];
    const float* L2_b       = (const float*)d_in[16];
    const float* Rf         = (const float*)d_in[17];
    const float* R1         = (const float*)d_in[18];
    const float* R2         = (const float*)d_in[19];
    const float* reg_b      = (const float*)d_in[20];

    int B = in_sizes[0] / NC;
    float* outf = (float*)d_out;

    // Kernel 1: fused precompute + finalize
    precompute_finalize_kernel<<<GRID1, 256>>>(W_enc, b_enc, W_shape, W_cam, W_phi, W_leaf, Rf,
                                               L1_w, L1_b, L2_w, L2_b, R1, R2,
                                               b_shape, b_cam, b_phi, b_leaf,
                                               init_shape, init_cam, reg_b);

    // Kernel 2: programmatic dependent launch (upstream triggers at entry;
    // downstream's griddepcontrol.wait enforces full upstream completion).
    cudaLaunchAttribute pssAttr[1];
    pssAttr[0].id = cudaLaunchAttributeProgrammaticStreamSerialization;
    pssAttr[0].val.programmaticStreamSerializationAllowed = 1;

    cudaLaunchConfig_t cfg = {};
    cfg.gridDim  = dim3((B + RPB - 1) / RPB, NSLICES);
    cfg.blockDim = dim3(TPB);
    cfg.attrs    = pssAttr;
    cfg.numAttrs = 1;
    cudaLaunchKernelEx(&cfg, main_kernel, joints, outf, B);
}